// round 6
// baseline (speedup 1.0000x reference)
#include <cuda_runtime.h>

#define NMAX   100000
#define EMAX   1600000
#define INH    18
#define OUTH   11
#define OUTP   12      // 11 features + dinv in slot 11
#define NCLASS 40
#define CDIM   51      // NCLASS + OUTH
#define NBLK_SCAN 128  // >= ceil(NMAX/1024) = 98

// ---------------- scratch (device globals; zero-init BSS) ----------------
__device__ int   g_cnt   [NMAX];       // in-degree; zeroed by agg1 each run
__device__ int   g_rowptr[NMAX];       // block-local exclusive scan of cnt
__device__ int   g_cur   [NMAX];       // scatter cursor; zeroed by agg1
__device__ int   g_blksum[NBLK_SCAN];
__device__ int   g_blkoff[NBLK_SCAN];
__device__ float g_dinv[NMAX];
__device__ float g_sdin[NMAX];
__device__ __align__(16) float g_M  [NMAX * OUTP];   // [m0..m10, dinv]
__device__ __align__(16) float g_Y1 [NMAX * OUTP];   // [y0..y10, dinv]
__device__ __align__(16) float g_Y2 [NMAX * OUTP];
__device__ int   g_esrc[EMAX];         // CSR src ids (dst-major)
__device__ float g_c  [OUTH];          // b1 @ W2

// ---------------- kernels ----------------

// 0: in-degree histogram, 4 edges/thread (cnt starts 0: BSS / agg1 of prev run)
__global__ void k_deg(const int* __restrict__ dst, int e) {
    int i = blockIdx.x * blockDim.x + threadIdx.x;
    int base = i * 4;
    if (base + 3 < e) {
        int4 d4 = *reinterpret_cast<const int4*>(dst + base);
        atomicAdd(&g_cnt[d4.x], 1);
        atomicAdd(&g_cnt[d4.y], 1);
        atomicAdd(&g_cnt[d4.z], 1);
        atomicAdd(&g_cnt[d4.w], 1);
    } else {
        for (int k = base; k < e; k++) atomicAdd(&g_cnt[dst[k]], 1);
    }
}

// 1: block-local exclusive scan (1024 elems/block), block sums out
__global__ void k_scan1(int n) {
    __shared__ int sh[256];
    int b = blockIdx.x, t = threadIdx.x;
    int base = b * 1024 + t * 4;
    int v0 = 0, v1 = 0, v2 = 0, v3 = 0;
    if (base + 3 < n) {
        int4 c = *reinterpret_cast<const int4*>(&g_cnt[base]);
        v0 = c.x; v1 = c.y; v2 = c.z; v3 = c.w;
    } else {
        if (base     < n) v0 = g_cnt[base];
        if (base + 1 < n) v1 = g_cnt[base + 1];
        if (base + 2 < n) v2 = g_cnt[base + 2];
        if (base + 3 < n) v3 = g_cnt[base + 3];
    }
    int tsum = v0 + v1 + v2 + v3;
    sh[t] = tsum;
    __syncthreads();
    for (int off = 1; off < 256; off <<= 1) {
        int x = (t >= off) ? sh[t - off] : 0;
        __syncthreads();
        sh[t] += x;
        __syncthreads();
    }
    int excl = sh[t] - tsum;
    if (t == 255) g_blksum[b] = sh[255];
    if (base     < n) g_rowptr[base]     = excl;
    if (base + 1 < n) g_rowptr[base + 1] = excl + v0;
    if (base + 2 < n) g_rowptr[base + 2] = excl + v0 + v1;
    if (base + 3 < n) g_rowptr[base + 3] = excl + v0 + v1 + v2;
}

// 2: scan of block sums
__global__ void k_scan2(int nblk) {
    __shared__ int sh[NBLK_SCAN];
    int t = threadIdx.x;
    int v = (t < nblk) ? g_blksum[t] : 0;
    sh[t] = v;
    __syncthreads();
    for (int off = 1; off < NBLK_SCAN; off <<= 1) {
        int x = (t >= off) ? sh[t - off] : 0;
        __syncthreads();
        sh[t] += x;
        __syncthreads();
    }
    g_blkoff[t] = sh[t] - v;   // exclusive
}

// 3: scatter src into CSR slots (counting sort by dst). cur starts 0.
__global__ void k_scatter(const int* __restrict__ ei, int e) {
    int i = blockIdx.x * blockDim.x + threadIdx.x;
    if (i >= e) return;
    int s = ei[i];
    int d = ei[e + i];
    int base = g_rowptr[d] + g_blkoff[d >> 10];
    int pos  = base + atomicAdd(&g_cur[d], 1);
    g_esrc[pos] = s;
}

// 4: dinv = rsqrt(cnt+1); M = [x @ W12, dinv]. W12/c recomputed per block.
__global__ void k_dinvM(const float* __restrict__ x,
                        const float* __restrict__ W1, const float* __restrict__ W2,
                        const float* __restrict__ b1, int nh, int n) {
    __shared__ float w[INH * OUTH];
    int t = threadIdx.x;
    if (t < INH * OUTH) {
        int i = t / OUTH, j = t % OUTH;
        float s = 0.f;
        for (int k = 0; k < nh; k++) s += W1[i * nh + k] * W2[k * OUTH + j];
        w[t] = s;
    } else if (t < INH * OUTH + OUTH && blockIdx.x == 0) {
        int j = t - INH * OUTH;
        float s = 0.f;
        for (int k = 0; k < nh; k++) s += b1[k] * W2[k * OUTH + j];
        g_c[j] = s;
    }
    __syncthreads();
    int i = blockIdx.x * blockDim.x + threadIdx.x;
    if (i >= n) return;
    float di = rsqrtf((float)(g_cnt[i] + 1));
    g_dinv[i] = di;
    float xr[INH];
#pragma unroll
    for (int k = 0; k < INH; k++) xr[k] = x[i * INH + k];
    float o[OUTP];
#pragma unroll
    for (int j = 0; j < OUTH; j++) {
        float s = 0.f;
#pragma unroll
        for (int k = 0; k < INH; k++) s += xr[k] * w[k * OUTH + j];
        o[j] = s;
    }
    o[OUTH] = di;                       // pack dinv in padding slot
    float4* mp = reinterpret_cast<float4*>(&g_M[i * OUTP]);
    mp[0] = make_float4(o[0], o[1], o[2],  o[3]);
    mp[1] = make_float4(o[4], o[5], o[6],  o[7]);
    mp[2] = make_float4(o[8], o[9], o[10], o[11]);
}

// 5: Y1[i] = di^2*M[i] + sum nrm*M[s]; Y1 slot11 = dinv; sdin from lane 11
__global__ void k_agg0(int n) {
    int tid  = blockIdx.x * blockDim.x + threadIdx.x;
    int node = tid >> 4;
    int lane = tid & 15;
    bool valid = (node < n);
    if (!valid) node = n - 1;           // clamp; keep warp converged for shfl
    int beg = g_rowptr[node] + g_blkoff[node >> 10];
    int cnt = g_cnt[node];
    float dd = g_dinv[node];
    float acc = 0.f;
#pragma unroll 4
    for (int k = 0; k < cnt; k++) {
        int s = __ldg(&g_esrc[beg + k]);
        float v = (lane < OUTP) ? __ldg(&g_M[s * OUTP + lane]) : 0.f;
        float ds = __shfl_sync(0xFFFFFFFFu, v, OUTH, 16);   // lane 11 = dinv[s]
        if (lane < OUTH)      acc += (ds * dd) * v;
        else if (lane == OUTH) acc += ds;                   // sum dinv[src]
    }
    if (!valid) return;
    if (lane < OUTH) {
        float mself = g_M[node * OUTP + lane];
        g_Y1[node * OUTP + lane] = dd * dd * mself + acc;
    } else if (lane == OUTH) {
        g_Y1[node * OUTP + OUTH] = dd;   // keep dinv packed in Y1
        g_sdin[node] = acc;
    }
}

// 6: Y2[i] = di^2*Y1[i] + sum nrm*Y1[s]; zero cnt/cur for next run
__global__ void k_agg1(int n) {
    int tid  = blockIdx.x * blockDim.x + threadIdx.x;
    int node = tid >> 4;
    int lane = tid & 15;
    bool valid = (node < n);
    if (!valid) node = n - 1;
    int beg = g_rowptr[node] + g_blkoff[node >> 10];
    int cnt = g_cnt[node];
    float dd = g_dinv[node];
    float acc = 0.f;
#pragma unroll 4
    for (int k = 0; k < cnt; k++) {
        int s = __ldg(&g_esrc[beg + k]);
        float v = (lane < OUTP) ? __ldg(&g_Y1[s * OUTP + lane]) : 0.f;
        float ds = __shfl_sync(0xFFFFFFFFu, v, OUTH, 16);
        if (lane < OUTH) acc += (ds * dd) * v;
    }
    if (!valid) return;
    if (lane < OUTH) {
        float yself = g_Y1[node * OUTP + lane];
        g_Y2[node * OUTP + lane] = dd * dd * yself + acc;
    } else if (lane == 14) {
        g_cnt[node] = 0;                 // restore replay invariant
    } else if (lane == 15) {
        g_cur[node] = 0;
    }
}

// 7: emb_b = relu(Y2 + s*c + b2);  out = [emb_a, emb_b] @ Wc + bc
__global__ void k_final(const float* __restrict__ emb_a, const float* __restrict__ b2,
                        const float* __restrict__ Wc, const float* __restrict__ bc,
                        float* __restrict__ out, int n) {
    __shared__ float wsm[CDIM * NCLASS];
    __shared__ float bsm[NCLASS];
    __shared__ float csm[OUTH];
    __shared__ float b2sm[OUTH];
    for (int t = threadIdx.x; t < CDIM * NCLASS; t += blockDim.x) wsm[t] = Wc[t];
    if (threadIdx.x < NCLASS) bsm[threadIdx.x] = bc[threadIdx.x];
    if (threadIdx.x < OUTH) { csm[threadIdx.x] = g_c[threadIdx.x]; b2sm[threadIdx.x] = b2[threadIdx.x]; }
    __syncthreads();
    int i = blockIdx.x * blockDim.x + threadIdx.x;
    if (i >= n) return;

    float acc[NCLASS];
#pragma unroll
    for (int k = 0; k < NCLASS; k++) acc[k] = bsm[k];

    const float4* ea = reinterpret_cast<const float4*>(&emb_a[(size_t)i * NCLASS]);
#pragma unroll
    for (int m4 = 0; m4 < NCLASS / 4; m4++) {
        float4 v = ea[m4];
        float vv[4] = {v.x, v.y, v.z, v.w};
#pragma unroll
        for (int q = 0; q < 4; q++) {
            float a = vv[q];
            int m = m4 * 4 + q;
#pragma unroll
            for (int k = 0; k < NCLASS; k++) acc[k] += a * wsm[m * NCLASS + k];
        }
    }

    float di = g_dinv[i];
    float s = di * (di + g_sdin[i]);
#pragma unroll
    for (int j = 0; j < OUTH; j++) {
        float h = g_Y2[(size_t)i * OUTP + j] + s * csm[j] + b2sm[j];
        h = fmaxf(h, 0.0f);
#pragma unroll
        for (int k = 0; k < NCLASS; k++) acc[k] += h * wsm[(NCLASS + j) * NCLASS + k];
    }

    float4* op = reinterpret_cast<float4*>(&out[(size_t)i * NCLASS]);
#pragma unroll
    for (int q = 0; q < NCLASS / 4; q++)
        op[q] = make_float4(acc[q * 4], acc[q * 4 + 1], acc[q * 4 + 2], acc[q * 4 + 3]);
}

// ---------------- launch ----------------
extern "C" void kernel_launch(void* const* d_in, const int* in_sizes, int n_in,
                              void* d_out, int out_size) {
    const float* x     = (const float*)d_in[0];
    const int*   ei    = (const int*)d_in[1];     // int32 (JAX x64 disabled)
    const float* emb_a = (const float*)d_in[2];
    const float* W1    = (const float*)d_in[3];
    const float* b1    = (const float*)d_in[4];
    const float* W2    = (const float*)d_in[5];
    const float* b2    = (const float*)d_in[6];
    const float* Wc    = (const float*)d_in[7];
    const float* bc    = (const float*)d_in[8];
    float* out = (float*)d_out;

    int n  = in_sizes[0] / INH;   // 100000
    int e  = in_sizes[1] / 2;     // 1600000
    int nh = in_sizes[4];         // 256

    const int TB = 256;
    int nblk = (n + 1023) / 1024;             // 98
    k_deg    <<<(e / 4 + TB - 1) / TB, TB>>>(ei + e, e);                 // 0
    k_scan1  <<<nblk, 256>>>(n);                                         // 1
    k_scan2  <<<1, NBLK_SCAN>>>(nblk);                                   // 2
    k_scatter<<<(e + TB - 1) / TB, TB>>>(ei, e);                         // 3 <- ncu
    k_dinvM  <<<(n + TB - 1) / TB, TB>>>(x, W1, W2, b1, nh, n);          // 4
    k_agg0   <<<(n * 16 + TB - 1) / TB, TB>>>(n);                        // 5
    k_agg1   <<<(n * 16 + TB - 1) / TB, TB>>>(n);                        // 6
    k_final  <<<(n + TB - 1) / TB, TB>>>(emb_a, b2, Wc, bc, out, n);     // 7
}

// round 7
// speedup vs baseline: 1.1719x; 1.1719x over previous
#include <cuda_runtime.h>

#define NMAX   100000
#define EMAX   1600000
#define INH    18
#define OUTH   11
#define OUTP   12      // 11 features + dinv in slot 11
#define NCLASS 40
#define CDIM   51      // NCLASS + OUTH
#define NBLK   98      // ceil(NMAX/1024)

// ---------------- scratch (device globals; zero-init BSS) ----------------
__device__ int   g_cnt   [NMAX];       // in-degree; re-zeroed by agg1 each run
__device__ int   g_rowptr[NMAX];       // block-local excl scan; bumped by scatter
__device__ int   g_blksum[NBLK];
__device__ int   g_blkoff[NBLK];
__device__ int   g_ctr;                // ticket; reset by scanM last block
__device__ float g_dinv[NMAX];
__device__ float g_sdin[NMAX];
__device__ __align__(16) float g_M  [NMAX * OUTP];   // [m0..m10, dinv]
__device__ __align__(16) float g_Y1 [NMAX * OUTP];   // [y0..y10, dinv]
__device__ __align__(16) float g_Y2 [NMAX * OUTP];
__device__ int   g_esrc[EMAX];         // CSR src ids (dst-major)
__device__ float g_c  [OUTH];          // b1 @ W2

// ---------------- kernels ----------------

// 0: in-degree histogram, 4 edges/thread
__global__ void k_deg(const int* __restrict__ dst, int e) {
    int i = blockIdx.x * blockDim.x + threadIdx.x;
    int base = i * 4;
    if ((e & 3) == 0 && base + 3 < e) {
        int4 d4 = *reinterpret_cast<const int4*>(dst + base);
        atomicAdd(&g_cnt[d4.x], 1);
        atomicAdd(&g_cnt[d4.y], 1);
        atomicAdd(&g_cnt[d4.z], 1);
        atomicAdd(&g_cnt[d4.w], 1);
    } else {
        for (int k = base; k < e && k < base + 4; k++) atomicAdd(&g_cnt[dst[k]], 1);
    }
}

// 1: fused: block-local scan of cnt -> rowptr; W12; dinv+M; last block scans blksums
__global__ void k_scanM(const float* __restrict__ x,
                        const float* __restrict__ W1, const float* __restrict__ W2,
                        const float* __restrict__ b1, int nh, int n) {
    __shared__ float w[INH * OUTH];
    __shared__ int   sh[256];
    __shared__ int   sh2[128];
    __shared__ int   lastblk;
    int b = blockIdx.x, t = threadIdx.x;
    int base = b * 1024 + t * 4;

    // ---- local exclusive scan of cnt (1024 per block) ----
    int v0 = 0, v1 = 0, v2 = 0, v3 = 0;
    if (base + 3 < n) {
        int4 c = *reinterpret_cast<const int4*>(&g_cnt[base]);
        v0 = c.x; v1 = c.y; v2 = c.z; v3 = c.w;
    } else {
        if (base     < n) v0 = g_cnt[base];
        if (base + 1 < n) v1 = g_cnt[base + 1];
        if (base + 2 < n) v2 = g_cnt[base + 2];
        if (base + 3 < n) v3 = g_cnt[base + 3];
    }
    int tsum = v0 + v1 + v2 + v3;
    sh[t] = tsum;
    __syncthreads();
    for (int off = 1; off < 256; off <<= 1) {
        int xx = (t >= off) ? sh[t - off] : 0;
        __syncthreads();
        sh[t] += xx;
        __syncthreads();
    }
    int excl = sh[t] - tsum;
    if (t == 255) g_blksum[b] = sh[255];
    if (base     < n) g_rowptr[base]     = excl;
    if (base + 1 < n) g_rowptr[base + 1] = excl + v0;
    if (base + 2 < n) g_rowptr[base + 2] = excl + v0 + v1;
    if (base + 3 < n) g_rowptr[base + 3] = excl + v0 + v1 + v2;

    // ---- W12 (and c on block 0) ----
    if (t < INH * OUTH) {
        int i = t / OUTH, j = t % OUTH;
        float s = 0.f;
        for (int k = 0; k < nh; k++) s += W1[i * nh + k] * W2[k * OUTH + j];
        w[t] = s;
    } else if (b == 0 && t < INH * OUTH + OUTH) {
        int j = t - INH * OUTH;
        float s = 0.f;
        for (int k = 0; k < nh; k++) s += b1[k] * W2[k * OUTH + j];
        g_c[j] = s;
    }
    __syncthreads();

    // ---- dinv + M for 4 nodes/thread ----
    int cn[4] = {v0, v1, v2, v3};
#pragma unroll
    for (int q = 0; q < 4; q++) {
        int node = base + q;
        if (node >= n) break;
        float di = rsqrtf((float)(cn[q] + 1));
        g_dinv[node] = di;
        float xr[INH];
#pragma unroll
        for (int k = 0; k < INH; k++) xr[k] = x[node * INH + k];
        float o[OUTP];
#pragma unroll
        for (int j = 0; j < OUTH; j++) {
            float s = 0.f;
#pragma unroll
            for (int k = 0; k < INH; k++) s += xr[k] * w[k * OUTH + j];
            o[j] = s;
        }
        o[OUTH] = di;
        float4* mp = reinterpret_cast<float4*>(&g_M[node * OUTP]);
        mp[0] = make_float4(o[0], o[1], o[2],  o[3]);
        mp[1] = make_float4(o[4], o[5], o[6],  o[7]);
        mp[2] = make_float4(o[8], o[9], o[10], o[11]);
    }

    // ---- ticket: last block scans the 98 block sums ----
    __syncthreads();
    if (t == 0) {
        __threadfence();
        lastblk = (atomicAdd(&g_ctr, 1) == gridDim.x - 1) ? 1 : 0;
    }
    __syncthreads();
    if (lastblk) {
        __threadfence();
        int v = 0;
        if (t < NBLK) v = g_blksum[t];
        if (t < 128) sh2[t] = (t < NBLK) ? v : 0;
        __syncthreads();
        for (int off = 1; off < 128; off <<= 1) {
            int xx = 0;
            if (t < 128 && t >= off) xx = sh2[t - off];
            __syncthreads();
            if (t < 128) sh2[t] += xx;
            __syncthreads();
        }
        if (t < NBLK) g_blkoff[t] = sh2[t] - v;   // exclusive
        if (t == 0) g_ctr = 0;                    // replay invariant
    }
}

// 2: scatter src into CSR (atomic directly on rowptr; no separate cursor)
__global__ void k_scatter(const int* __restrict__ ei, int e) {
    int i = blockIdx.x * blockDim.x + threadIdx.x;
    int base = i * 4;
    if ((e & 3) == 0 && base + 3 < e) {
        int4 s4 = *reinterpret_cast<const int4*>(ei + base);
        int4 d4 = *reinterpret_cast<const int4*>(ei + e + base);
        int p;
        p = atomicAdd(&g_rowptr[d4.x], 1) + g_blkoff[d4.x >> 10]; g_esrc[p] = s4.x;
        p = atomicAdd(&g_rowptr[d4.y], 1) + g_blkoff[d4.y >> 10]; g_esrc[p] = s4.y;
        p = atomicAdd(&g_rowptr[d4.z], 1) + g_blkoff[d4.z >> 10]; g_esrc[p] = s4.z;
        p = atomicAdd(&g_rowptr[d4.w], 1) + g_blkoff[d4.w >> 10]; g_esrc[p] = s4.w;
    } else {
        for (int k = base; k < e && k < base + 4; k++) {
            int s = ei[k], d = ei[e + k];
            int p = atomicAdd(&g_rowptr[d], 1) + g_blkoff[d >> 10];
            g_esrc[p] = s;
        }
    }
}

// 3: Y1[i] = dd*(dd*M[i] + sum ds*M[s]); Y1 slot11 = dd; sdin = sum ds
__global__ void k_agg0(int n) {
    int tid  = blockIdx.x * blockDim.x + threadIdx.x;
    int node = tid >> 4;
    int lane = tid & 15;
    if (node >= n) return;
    unsigned hmask = 0xFFFFu << (threadIdx.x & 16);
    int   cnt = g_cnt[node];
    int   beg = g_rowptr[node] + g_blkoff[node >> 10] - cnt;  // rowptr was bumped
    float dd  = g_dinv[node];
    float acc = 0.f;
#pragma unroll 4
    for (int k = 0; k < cnt; k++) {
        int s = __ldg(&g_esrc[beg + k]);
        float v = (lane < OUTP) ? __ldg(&g_M[s * OUTP + lane]) : 0.f;
        float ds = __shfl_sync(hmask, v, OUTH, 16);   // lane 11 holds dinv[s]
        acc += (lane == OUTH) ? v : ds * v;
    }
    if (lane < OUTH) {
        float m = g_M[node * OUTP + lane];
        g_Y1[node * OUTP + lane] = dd * (dd * m + acc);
    } else if (lane == OUTH) {
        g_Y1[node * OUTP + OUTH] = dd;
        g_sdin[node] = acc;
    }
}

// 4: Y2[i] = dd*(dd*Y1[i] + sum ds*Y1[s]); zero cnt for next run
__global__ void k_agg1(int n) {
    int tid  = blockIdx.x * blockDim.x + threadIdx.x;
    int node = tid >> 4;
    int lane = tid & 15;
    if (node >= n) return;
    unsigned hmask = 0xFFFFu << (threadIdx.x & 16);
    int   cnt = g_cnt[node];
    int   beg = g_rowptr[node] + g_blkoff[node >> 10] - cnt;
    float dd  = g_dinv[node];
    float acc = 0.f;
#pragma unroll 4
    for (int k = 0; k < cnt; k++) {
        int s = __ldg(&g_esrc[beg + k]);
        float v = (lane < OUTP) ? __ldg(&g_Y1[s * OUTP + lane]) : 0.f;
        float ds = __shfl_sync(hmask, v, OUTH, 16);
        acc += ds * v;
    }
    if (lane < OUTH) {
        float y1 = g_Y1[node * OUTP + lane];
        g_Y2[node * OUTP + lane] = dd * (dd * y1 + acc);
    } else if (lane == 12) {
        g_cnt[node] = 0;                 // replay invariant
    }
}

// 5: emb_b = relu(Y2 + s*c + b2);  out = [emb_a, emb_b] @ Wc + bc
__global__ void k_final(const float* __restrict__ emb_a, const float* __restrict__ b2,
                        const float* __restrict__ Wc, const float* __restrict__ bc,
                        float* __restrict__ out, int n) {
    __shared__ float wsm[CDIM * NCLASS];
    __shared__ float bsm[NCLASS];
    __shared__ float csm[OUTH];
    __shared__ float b2sm[OUTH];
    for (int t = threadIdx.x; t < CDIM * NCLASS; t += blockDim.x) wsm[t] = Wc[t];
    if (threadIdx.x < NCLASS) bsm[threadIdx.x] = bc[threadIdx.x];
    if (threadIdx.x < OUTH) { csm[threadIdx.x] = g_c[threadIdx.x]; b2sm[threadIdx.x] = b2[threadIdx.x]; }
    __syncthreads();
    int i = blockIdx.x * blockDim.x + threadIdx.x;
    if (i >= n) return;

    float acc[NCLASS];
#pragma unroll
    for (int k = 0; k < NCLASS; k++) acc[k] = bsm[k];

    const float4* ea = reinterpret_cast<const float4*>(&emb_a[(size_t)i * NCLASS]);
#pragma unroll
    for (int m4 = 0; m4 < NCLASS / 4; m4++) {
        float4 v = ea[m4];
        float vv[4] = {v.x, v.y, v.z, v.w};
#pragma unroll
        for (int q = 0; q < 4; q++) {
            float a = vv[q];
            int m = m4 * 4 + q;
#pragma unroll
            for (int k = 0; k < NCLASS; k++) acc[k] += a * wsm[m * NCLASS + k];
        }
    }

    float di = g_dinv[i];
    float s = di * (di + g_sdin[i]);
#pragma unroll
    for (int j = 0; j < OUTH; j++) {
        float h = g_Y2[(size_t)i * OUTP + j] + s * csm[j] + b2sm[j];
        h = fmaxf(h, 0.0f);
#pragma unroll
        for (int k = 0; k < NCLASS; k++) acc[k] += h * wsm[(NCLASS + j) * NCLASS + k];
    }

    float4* op = reinterpret_cast<float4*>(&out[(size_t)i * NCLASS]);
#pragma unroll
    for (int q = 0; q < NCLASS / 4; q++)
        op[q] = make_float4(acc[q * 4], acc[q * 4 + 1], acc[q * 4 + 2], acc[q * 4 + 3]);
}

// ---------------- launch ----------------
extern "C" void kernel_launch(void* const* d_in, const int* in_sizes, int n_in,
                              void* d_out, int out_size) {
    const float* x     = (const float*)d_in[0];
    const int*   ei    = (const int*)d_in[1];     // int32 (JAX x64 disabled)
    const float* emb_a = (const float*)d_in[2];
    const float* W1    = (const float*)d_in[3];
    const float* b1    = (const float*)d_in[4];
    const float* W2    = (const float*)d_in[5];
    const float* b2    = (const float*)d_in[6];
    const float* Wc    = (const float*)d_in[7];
    const float* bc    = (const float*)d_in[8];
    float* out = (float*)d_out;

    int n  = in_sizes[0] / INH;   // 100000
    int e  = in_sizes[1] / 2;     // 1600000
    int nh = in_sizes[4];         // 256

    const int TB = 256;
    int nblk = (n + 1023) / 1024;             // 98
    k_deg    <<<(e / 4 + TB - 1) / TB, TB>>>(ei + e, e);                 // 0
    k_scanM  <<<nblk, 256>>>(x, W1, W2, b1, nh, n);                      // 1
    k_scatter<<<(e / 4 + TB - 1) / TB, TB>>>(ei, e);                     // 2
    k_agg0   <<<(n * 16 + TB - 1) / TB, TB>>>(n);                        // 3 <- ncu
    k_agg1   <<<(n * 16 + TB - 1) / TB, TB>>>(n);                        // 4
    k_final  <<<(n + TB - 1) / TB, TB>>>(emb_a, b2, Wc, bc, out, n);     // 5
}

// round 8
// speedup vs baseline: 1.3115x; 1.1191x over previous
#include <cuda_runtime.h>

#define NMAX   100000
#define EMAX   1600000
#define INH    18
#define OUTH   11
#define OUTP   12      // 11 features + dinv in slot 11
#define NCLASS 40
#define CDIM   51      // NCLASS + OUTH
#define NBLK   98      // ceil(NMAX/1024)

// ---------------- scratch (device globals; zero-init BSS) ----------------
__device__ int   g_cnt   [NMAX];       // in-degree; re-zeroed by agg1 each run
__device__ int   g_rowptr[NMAX];       // block-local excl scan; bumped by scatter
__device__ int   g_blksum[NBLK];
__device__ int   g_blkoff[NBLK];
__device__ int   g_ctr;                // ticket; reset by scanM last block
__device__ float g_dinv[NMAX];
__device__ float g_sdin[NMAX];
__device__ __align__(16) float g_M  [NMAX * OUTP];   // [m0..m10, dinv]
__device__ __align__(16) float g_Y1 [NMAX * OUTP];   // [y0..y10, dinv]
__device__ __align__(16) float g_Y2 [NMAX * OUTP];
__device__ int   g_esrc[EMAX];         // CSR src ids (dst-major)
__device__ float g_c  [OUTH];          // b1 @ W2

// ---------------- kernels ----------------

// 0: in-degree histogram, 4 edges/thread
__global__ void k_deg(const int* __restrict__ dst, int e) {
    int i = blockIdx.x * blockDim.x + threadIdx.x;
    int base = i * 4;
    if ((e & 3) == 0 && base + 3 < e) {
        int4 d4 = *reinterpret_cast<const int4*>(dst + base);
        atomicAdd(&g_cnt[d4.x], 1);
        atomicAdd(&g_cnt[d4.y], 1);
        atomicAdd(&g_cnt[d4.z], 1);
        atomicAdd(&g_cnt[d4.w], 1);
    } else {
        for (int k = base; k < e && k < base + 4; k++) atomicAdd(&g_cnt[dst[k]], 1);
    }
}

// 1: fused: block-local scan of cnt -> rowptr; W12; dinv+M; last block scans blksums
__global__ void k_scanM(const float* __restrict__ x,
                        const float* __restrict__ W1, const float* __restrict__ W2,
                        const float* __restrict__ b1, int nh, int n) {
    __shared__ float w[INH * OUTH];
    __shared__ int   sh[256];
    __shared__ int   sh2[128];
    __shared__ int   lastblk;
    int b = blockIdx.x, t = threadIdx.x;
    int base = b * 1024 + t * 4;

    // ---- local exclusive scan of cnt (1024 per block) ----
    int v0 = 0, v1 = 0, v2 = 0, v3 = 0;
    if (base + 3 < n) {
        int4 c = *reinterpret_cast<const int4*>(&g_cnt[base]);
        v0 = c.x; v1 = c.y; v2 = c.z; v3 = c.w;
    } else {
        if (base     < n) v0 = g_cnt[base];
        if (base + 1 < n) v1 = g_cnt[base + 1];
        if (base + 2 < n) v2 = g_cnt[base + 2];
        if (base + 3 < n) v3 = g_cnt[base + 3];
    }
    int tsum = v0 + v1 + v2 + v3;
    sh[t] = tsum;
    __syncthreads();
    for (int off = 1; off < 256; off <<= 1) {
        int xx = (t >= off) ? sh[t - off] : 0;
        __syncthreads();
        sh[t] += xx;
        __syncthreads();
    }
    int excl = sh[t] - tsum;
    if (t == 255) g_blksum[b] = sh[255];
    if (base     < n) g_rowptr[base]     = excl;
    if (base + 1 < n) g_rowptr[base + 1] = excl + v0;
    if (base + 2 < n) g_rowptr[base + 2] = excl + v0 + v1;
    if (base + 3 < n) g_rowptr[base + 3] = excl + v0 + v1 + v2;

    // ---- W12 (and c on block 0) ----
    if (t < INH * OUTH) {
        int i = t / OUTH, j = t % OUTH;
        float s = 0.f;
        for (int k = 0; k < nh; k++) s += W1[i * nh + k] * W2[k * OUTH + j];
        w[t] = s;
    } else if (b == 0 && t < INH * OUTH + OUTH) {
        int j = t - INH * OUTH;
        float s = 0.f;
        for (int k = 0; k < nh; k++) s += b1[k] * W2[k * OUTH + j];
        g_c[j] = s;
    }
    __syncthreads();

    // ---- dinv + M for 4 nodes/thread ----
    int cn[4] = {v0, v1, v2, v3};
#pragma unroll
    for (int q = 0; q < 4; q++) {
        int node = base + q;
        if (node >= n) break;
        float di = rsqrtf((float)(cn[q] + 1));
        g_dinv[node] = di;
        float xr[INH];
#pragma unroll
        for (int k = 0; k < INH; k++) xr[k] = x[node * INH + k];
        float o[OUTP];
#pragma unroll
        for (int j = 0; j < OUTH; j++) {
            float s = 0.f;
#pragma unroll
            for (int k = 0; k < INH; k++) s += xr[k] * w[k * OUTH + j];
            o[j] = s;
        }
        o[OUTH] = di;
        float4* mp = reinterpret_cast<float4*>(&g_M[node * OUTP]);
        mp[0] = make_float4(o[0], o[1], o[2],  o[3]);
        mp[1] = make_float4(o[4], o[5], o[6],  o[7]);
        mp[2] = make_float4(o[8], o[9], o[10], o[11]);
    }

    // ---- ticket: last block scans the 98 block sums ----
    __syncthreads();
    if (t == 0) {
        __threadfence();
        lastblk = (atomicAdd(&g_ctr, 1) == gridDim.x - 1) ? 1 : 0;
    }
    __syncthreads();
    if (lastblk) {
        __threadfence();
        int v = 0;
        if (t < NBLK) v = g_blksum[t];
        if (t < 128) sh2[t] = (t < NBLK) ? v : 0;
        __syncthreads();
        for (int off = 1; off < 128; off <<= 1) {
            int xx = 0;
            if (t < 128 && t >= off) xx = sh2[t - off];
            __syncthreads();
            if (t < 128) sh2[t] += xx;
            __syncthreads();
        }
        if (t < NBLK) g_blkoff[t] = sh2[t] - v;   // exclusive
        if (t == 0) g_ctr = 0;                    // replay invariant
    }
}

// 2: scatter src into CSR (atomic directly on rowptr; no separate cursor)
__global__ void k_scatter(const int* __restrict__ ei, int e) {
    int i = blockIdx.x * blockDim.x + threadIdx.x;
    int base = i * 4;
    if ((e & 3) == 0 && base + 3 < e) {
        int4 s4 = *reinterpret_cast<const int4*>(ei + base);
        int4 d4 = *reinterpret_cast<const int4*>(ei + e + base);
        int p;
        p = atomicAdd(&g_rowptr[d4.x], 1) + g_blkoff[d4.x >> 10]; g_esrc[p] = s4.x;
        p = atomicAdd(&g_rowptr[d4.y], 1) + g_blkoff[d4.y >> 10]; g_esrc[p] = s4.y;
        p = atomicAdd(&g_rowptr[d4.z], 1) + g_blkoff[d4.z >> 10]; g_esrc[p] = s4.z;
        p = atomicAdd(&g_rowptr[d4.w], 1) + g_blkoff[d4.w >> 10]; g_esrc[p] = s4.w;
    } else {
        for (int k = base; k < e && k < base + 4; k++) {
            int s = ei[k], d = ei[e + k];
            int p = atomicAdd(&g_rowptr[d], 1) + g_blkoff[d >> 10];
            g_esrc[p] = s;
        }
    }
}

// 3: 4 lanes/node. Y1[i] = dd*(dd*M[i] + sum ds*M[s]); slot11 = dd; sdin = sum ds
__global__ void k_agg0(int n) {
    int tid  = blockIdx.x * blockDim.x + threadIdx.x;
    int node = tid >> 2;
    int lane = tid & 3;
    if (node >= n) return;
    unsigned gmask = 0xFu << (threadIdx.x & 28);   // this 4-lane group
    int   cnt = g_cnt[node];
    int   beg = g_rowptr[node] + g_blkoff[node >> 10] - cnt;  // rowptr was bumped
    float dd  = g_dinv[node];
    float4 acc = make_float4(0.f, 0.f, 0.f, 0.f);
    float  sds = 0.f;
#pragma unroll 4
    for (int k = 0; k < cnt; k++) {
        int s = __ldg(&g_esrc[beg + k]);
        float4 v = make_float4(0.f, 0.f, 0.f, 0.f);
        if (lane < 3) v = __ldg(reinterpret_cast<const float4*>(&g_M[s * OUTP]) + lane);
        float ds = __shfl_sync(gmask, v.w, 2, 4);   // lane2.w = dinv[s]
        acc.x += ds * v.x; acc.y += ds * v.y;
        acc.z += ds * v.z; acc.w += ds * v.w;
        sds += ds;
    }
    if (lane < 3) {
        float4 m = *(reinterpret_cast<const float4*>(&g_M[node * OUTP]) + lane);
        float4 y;
        y.x = dd * (dd * m.x + acc.x);
        y.y = dd * (dd * m.y + acc.y);
        y.z = dd * (dd * m.z + acc.z);
        y.w = dd * (dd * m.w + acc.w);
        if (lane == 2) y.w = dd;         // keep dinv packed in Y1 slot 11
        *(reinterpret_cast<float4*>(&g_Y1[node * OUTP]) + lane) = y;
    } else {
        g_sdin[node] = sds;
    }
}

// 4: Y2[i] = dd*(dd*Y1[i] + sum ds*Y1[s]); zero cnt for next run
__global__ void k_agg1(int n) {
    int tid  = blockIdx.x * blockDim.x + threadIdx.x;
    int node = tid >> 2;
    int lane = tid & 3;
    if (node >= n) return;
    unsigned gmask = 0xFu << (threadIdx.x & 28);
    int   cnt = g_cnt[node];
    int   beg = g_rowptr[node] + g_blkoff[node >> 10] - cnt;
    float dd  = g_dinv[node];
    float4 acc = make_float4(0.f, 0.f, 0.f, 0.f);
#pragma unroll 4
    for (int k = 0; k < cnt; k++) {
        int s = __ldg(&g_esrc[beg + k]);
        float4 v = make_float4(0.f, 0.f, 0.f, 0.f);
        if (lane < 3) v = __ldg(reinterpret_cast<const float4*>(&g_Y1[s * OUTP]) + lane);
        float ds = __shfl_sync(gmask, v.w, 2, 4);
        acc.x += ds * v.x; acc.y += ds * v.y;
        acc.z += ds * v.z; acc.w += ds * v.w;
    }
    if (lane < 3) {
        float4 y1 = *(reinterpret_cast<const float4*>(&g_Y1[node * OUTP]) + lane);
        float4 y;
        y.x = dd * (dd * y1.x + acc.x);
        y.y = dd * (dd * y1.y + acc.y);
        y.z = dd * (dd * y1.z + acc.z);
        y.w = dd * (dd * y1.w + acc.w);
        *(reinterpret_cast<float4*>(&g_Y2[node * OUTP]) + lane) = y;
    } else {
        g_cnt[node] = 0;                 // replay invariant
    }
}

// 5: emb_b = relu(Y2 + s*c + b2);  out = [emb_a, emb_b] @ Wc + bc
__global__ void k_final(const float* __restrict__ emb_a, const float* __restrict__ b2,
                        const float* __restrict__ Wc, const float* __restrict__ bc,
                        float* __restrict__ out, int n) {
    __shared__ float wsm[CDIM * NCLASS];
    __shared__ float bsm[NCLASS];
    __shared__ float csm[OUTH];
    __shared__ float b2sm[OUTH];
    for (int t = threadIdx.x; t < CDIM * NCLASS; t += blockDim.x) wsm[t] = Wc[t];
    if (threadIdx.x < NCLASS) bsm[threadIdx.x] = bc[threadIdx.x];
    if (threadIdx.x < OUTH) { csm[threadIdx.x] = g_c[threadIdx.x]; b2sm[threadIdx.x] = b2[threadIdx.x]; }
    __syncthreads();
    int i = blockIdx.x * blockDim.x + threadIdx.x;
    if (i >= n) return;

    float acc[NCLASS];
#pragma unroll
    for (int k = 0; k < NCLASS; k++) acc[k] = bsm[k];

    const float4* ea = reinterpret_cast<const float4*>(&emb_a[(size_t)i * NCLASS]);
#pragma unroll
    for (int m4 = 0; m4 < NCLASS / 4; m4++) {
        float4 v = ea[m4];
        float vv[4] = {v.x, v.y, v.z, v.w};
#pragma unroll
        for (int q = 0; q < 4; q++) {
            float a = vv[q];
            int m = m4 * 4 + q;
#pragma unroll
            for (int k = 0; k < NCLASS; k++) acc[k] += a * wsm[m * NCLASS + k];
        }
    }

    float di = g_dinv[i];
    float s = di * (di + g_sdin[i]);
#pragma unroll
    for (int j = 0; j < OUTH; j++) {
        float h = g_Y2[(size_t)i * OUTP + j] + s * csm[j] + b2sm[j];
        h = fmaxf(h, 0.0f);
#pragma unroll
        for (int k = 0; k < NCLASS; k++) acc[k] += h * wsm[(NCLASS + j) * NCLASS + k];
    }

    float4* op = reinterpret_cast<float4*>(&out[(size_t)i * NCLASS]);
#pragma unroll
    for (int q = 0; q < NCLASS / 4; q++)
        op[q] = make_float4(acc[q * 4], acc[q * 4 + 1], acc[q * 4 + 2], acc[q * 4 + 3]);
}

// ---------------- launch ----------------
extern "C" void kernel_launch(void* const* d_in, const int* in_sizes, int n_in,
                              void* d_out, int out_size) {
    const float* x     = (const float*)d_in[0];
    const int*   ei    = (const int*)d_in[1];     // int32 (JAX x64 disabled)
    const float* emb_a = (const float*)d_in[2];
    const float* W1    = (const float*)d_in[3];
    const float* b1    = (const float*)d_in[4];
    const float* W2    = (const float*)d_in[5];
    const float* b2    = (const float*)d_in[6];
    const float* Wc    = (const float*)d_in[7];
    const float* bc    = (const float*)d_in[8];
    float* out = (float*)d_out;

    int n  = in_sizes[0] / INH;   // 100000
    int e  = in_sizes[1] / 2;     // 1600000
    int nh = in_sizes[4];         // 256

    const int TB = 256;
    int nblk = (n + 1023) / 1024;             // 98
    k_deg    <<<(e / 4 + TB - 1) / TB, TB>>>(ei + e, e);                 // 0
    k_scanM  <<<nblk, 256>>>(x, W1, W2, b1, nh, n);                      // 1
    k_scatter<<<(e / 4 + TB - 1) / TB, TB>>>(ei, e);                     // 2
    k_agg0   <<<(n * 4 + TB - 1) / TB, TB>>>(n);                         // 3 <- ncu
    k_agg1   <<<(n * 4 + TB - 1) / TB, TB>>>(n);                         // 4
    k_final  <<<(n + TB - 1) / TB, TB>>>(emb_a, b2, Wc, bc, out, n);     // 5
}

// round 9
// speedup vs baseline: 1.3129x; 1.0011x over previous
#include <cuda_runtime.h>

#define NMAX   100000
#define EMAX   1600000
#define INH    18
#define OUTH   11
#define OUTP   12      // 11 features + dinv in slot 11
#define NCLASS 40
#define CDIM   51      // NCLASS + OUTH
#define NBLK   98      // ceil(NMAX/1024)

// ---------------- scratch (device globals; zero-init BSS) ----------------
__device__ int   g_cnt   [NMAX];       // in-degree; re-zeroed by agg1 each run
__device__ int   g_rowptr[NMAX];       // block-local excl scan; bumped by scatter
__device__ int   g_blksum[NBLK];
__device__ int   g_blkoff[NBLK];
__device__ int   g_ctr;                // ticket; reset by scanM last block
__device__ float g_dinv[NMAX];
__device__ float g_sdin[NMAX];
__device__ __align__(16) float g_M  [NMAX * OUTP];   // [m0..m10, dinv]
__device__ __align__(16) float g_Y1 [NMAX * OUTP];   // [y0..y10, dinv]
__device__ __align__(16) float g_Y2 [NMAX * OUTP];
__device__ int   g_esrc[EMAX];         // CSR src ids (dst-major)
__device__ float g_c  [OUTH];          // b1 @ W2

// ---------------- kernels ----------------

// 0: in-degree histogram, 4 edges/thread
__global__ void k_deg(const int* __restrict__ dst, int e) {
    int i = blockIdx.x * blockDim.x + threadIdx.x;
    int base = i * 4;
    if ((e & 3) == 0 && base + 3 < e) {
        int4 d4 = *reinterpret_cast<const int4*>(dst + base);
        atomicAdd(&g_cnt[d4.x], 1);
        atomicAdd(&g_cnt[d4.y], 1);
        atomicAdd(&g_cnt[d4.z], 1);
        atomicAdd(&g_cnt[d4.w], 1);
    } else {
        for (int k = base; k < e && k < base + 4; k++) atomicAdd(&g_cnt[dst[k]], 1);
    }
}

// 1: fused: block-local scan of cnt -> rowptr; W12; dinv+M; last block scans blksums
__global__ void k_scanM(const float* __restrict__ x,
                        const float* __restrict__ W1, const float* __restrict__ W2,
                        const float* __restrict__ b1, int nh, int n) {
    __shared__ float w[INH * OUTH];
    __shared__ int   sh[256];
    __shared__ int   sh2[128];
    __shared__ int   lastblk;
    int b = blockIdx.x, t = threadIdx.x;
    int base = b * 1024 + t * 4;

    int v0 = 0, v1 = 0, v2 = 0, v3 = 0;
    if (base + 3 < n) {
        int4 c = *reinterpret_cast<const int4*>(&g_cnt[base]);
        v0 = c.x; v1 = c.y; v2 = c.z; v3 = c.w;
    } else {
        if (base     < n) v0 = g_cnt[base];
        if (base + 1 < n) v1 = g_cnt[base + 1];
        if (base + 2 < n) v2 = g_cnt[base + 2];
        if (base + 3 < n) v3 = g_cnt[base + 3];
    }
    int tsum = v0 + v1 + v2 + v3;
    sh[t] = tsum;
    __syncthreads();
    for (int off = 1; off < 256; off <<= 1) {
        int xx = (t >= off) ? sh[t - off] : 0;
        __syncthreads();
        sh[t] += xx;
        __syncthreads();
    }
    int excl = sh[t] - tsum;
    if (t == 255) g_blksum[b] = sh[255];
    if (base     < n) g_rowptr[base]     = excl;
    if (base + 1 < n) g_rowptr[base + 1] = excl + v0;
    if (base + 2 < n) g_rowptr[base + 2] = excl + v0 + v1;
    if (base + 3 < n) g_rowptr[base + 3] = excl + v0 + v1 + v2;

    if (t < INH * OUTH) {
        int i = t / OUTH, j = t % OUTH;
        float s = 0.f;
        for (int k = 0; k < nh; k++) s += W1[i * nh + k] * W2[k * OUTH + j];
        w[t] = s;
    } else if (b == 0 && t < INH * OUTH + OUTH) {
        int j = t - INH * OUTH;
        float s = 0.f;
        for (int k = 0; k < nh; k++) s += b1[k] * W2[k * OUTH + j];
        g_c[j] = s;
    }
    __syncthreads();

    int cn[4] = {v0, v1, v2, v3};
#pragma unroll
    for (int q = 0; q < 4; q++) {
        int node = base + q;
        if (node >= n) break;
        float di = rsqrtf((float)(cn[q] + 1));
        g_dinv[node] = di;
        float xr[INH];
#pragma unroll
        for (int k = 0; k < INH; k++) xr[k] = x[node * INH + k];
        float o[OUTP];
#pragma unroll
        for (int j = 0; j < OUTH; j++) {
            float s = 0.f;
#pragma unroll
            for (int k = 0; k < INH; k++) s += xr[k] * w[k * OUTH + j];
            o[j] = s;
        }
        o[OUTH] = di;
        float4* mp = reinterpret_cast<float4*>(&g_M[node * OUTP]);
        mp[0] = make_float4(o[0], o[1], o[2],  o[3]);
        mp[1] = make_float4(o[4], o[5], o[6],  o[7]);
        mp[2] = make_float4(o[8], o[9], o[10], o[11]);
    }

    __syncthreads();
    if (t == 0) {
        __threadfence();
        lastblk = (atomicAdd(&g_ctr, 1) == gridDim.x - 1) ? 1 : 0;
    }
    __syncthreads();
    if (lastblk) {
        __threadfence();
        int v = 0;
        if (t < NBLK) v = g_blksum[t];
        if (t < 128) sh2[t] = (t < NBLK) ? v : 0;
        __syncthreads();
        for (int off = 1; off < 128; off <<= 1) {
            int xx = 0;
            if (t < 128 && t >= off) xx = sh2[t - off];
            __syncthreads();
            if (t < 128) sh2[t] += xx;
            __syncthreads();
        }
        if (t < NBLK) g_blkoff[t] = sh2[t] - v;
        if (t == 0) g_ctr = 0;
    }
}

// 2: scatter src into CSR (atomic directly on rowptr)
__global__ void k_scatter(const int* __restrict__ ei, int e) {
    int i = blockIdx.x * blockDim.x + threadIdx.x;
    int base = i * 4;
    if ((e & 3) == 0 && base + 3 < e) {
        int4 s4 = *reinterpret_cast<const int4*>(ei + base);
        int4 d4 = *reinterpret_cast<const int4*>(ei + e + base);
        int p;
        p = atomicAdd(&g_rowptr[d4.x], 1) + g_blkoff[d4.x >> 10]; g_esrc[p] = s4.x;
        p = atomicAdd(&g_rowptr[d4.y], 1) + g_blkoff[d4.y >> 10]; g_esrc[p] = s4.y;
        p = atomicAdd(&g_rowptr[d4.z], 1) + g_blkoff[d4.z >> 10]; g_esrc[p] = s4.z;
        p = atomicAdd(&g_rowptr[d4.w], 1) + g_blkoff[d4.w >> 10]; g_esrc[p] = s4.w;
    } else {
        for (int k = base; k < e && k < base + 4; k++) {
            int s = ei[k], d = ei[e + k];
            int p = atomicAdd(&g_rowptr[d], 1) + g_blkoff[d >> 10];
            g_esrc[p] = s;
        }
    }
}

// 3: 8 lanes/node (two quads: even/odd edges). Y1 = dd*(dd*M + sum ds*M[s])
__global__ void k_agg0(int n) {
    int tid  = blockIdx.x * blockDim.x + threadIdx.x;
    int node = tid >> 3;
    int ol   = tid & 7;            // octet lane
    int part = ol & 3;             // float4 index within quad (3 = sds lane)
    if (node >= n) return;
    unsigned qmask = 0xFu  << (threadIdx.x & 28);   // own quad
    unsigned omask = 0xFFu << (threadIdx.x & 24);   // own octet
    int   cnt = g_cnt[node];
    int   beg = g_rowptr[node] + g_blkoff[node >> 10] - cnt;  // rowptr was bumped
    float dd  = g_dinv[node];
    float4 acc = make_float4(0.f, 0.f, 0.f, 0.f);
    float  sds = 0.f;
    for (int k = (ol >> 2); k < cnt; k += 2) {      // quad A: even, quad B: odd
        int s = __ldg(&g_esrc[beg + k]);
        float4 v = make_float4(0.f, 0.f, 0.f, 0.f);
        if (part < 3) v = __ldg(reinterpret_cast<const float4*>(&g_M[s * OUTP]) + part);
        float ds = __shfl_sync(qmask, v.w, 2, 4);   // quad-local: lane2.w = dinv[s]
        acc.x += ds * v.x; acc.y += ds * v.y;
        acc.z += ds * v.z; acc.w += ds * v.w;
        sds += ds;
    }
    // combine quads (lanes 0-3 += lanes 4-7)
    acc.x += __shfl_down_sync(omask, acc.x, 4, 8);
    acc.y += __shfl_down_sync(omask, acc.y, 4, 8);
    acc.z += __shfl_down_sync(omask, acc.z, 4, 8);
    acc.w += __shfl_down_sync(omask, acc.w, 4, 8);
    sds   += __shfl_down_sync(omask, sds,   4, 8);
    if (ol < 3) {
        float4 m = *(reinterpret_cast<const float4*>(&g_M[node * OUTP]) + ol);
        float4 y;
        y.x = dd * (dd * m.x + acc.x);
        y.y = dd * (dd * m.y + acc.y);
        y.z = dd * (dd * m.z + acc.z);
        y.w = dd * (dd * m.w + acc.w);
        if (ol == 2) y.w = dd;          // keep dinv packed in Y1 slot 11
        *(reinterpret_cast<float4*>(&g_Y1[node * OUTP]) + ol) = y;
    } else if (ol == 3) {
        g_sdin[node] = sds;
    }
}

// 4: same layout. Y2 = dd*(dd*Y1 + sum ds*Y1[s]); zero cnt for next run
__global__ void k_agg1(int n) {
    int tid  = blockIdx.x * blockDim.x + threadIdx.x;
    int node = tid >> 3;
    int ol   = tid & 7;
    int part = ol & 3;
    if (node >= n) return;
    unsigned qmask = 0xFu  << (threadIdx.x & 28);
    unsigned omask = 0xFFu << (threadIdx.x & 24);
    int   cnt = g_cnt[node];
    int   beg = g_rowptr[node] + g_blkoff[node >> 10] - cnt;
    float dd  = g_dinv[node];
    float4 acc = make_float4(0.f, 0.f, 0.f, 0.f);
    for (int k = (ol >> 2); k < cnt; k += 2) {
        int s = __ldg(&g_esrc[beg + k]);
        float4 v = make_float4(0.f, 0.f, 0.f, 0.f);
        if (part < 3) v = __ldg(reinterpret_cast<const float4*>(&g_Y1[s * OUTP]) + part);
        float ds = __shfl_sync(qmask, v.w, 2, 4);
        acc.x += ds * v.x; acc.y += ds * v.y;
        acc.z += ds * v.z; acc.w += ds * v.w;
    }
    acc.x += __shfl_down_sync(omask, acc.x, 4, 8);
    acc.y += __shfl_down_sync(omask, acc.y, 4, 8);
    acc.z += __shfl_down_sync(omask, acc.z, 4, 8);
    acc.w += __shfl_down_sync(omask, acc.w, 4, 8);
    if (ol < 3) {
        float4 y1 = *(reinterpret_cast<const float4*>(&g_Y1[node * OUTP]) + ol);
        float4 y;
        y.x = dd * (dd * y1.x + acc.x);
        y.y = dd * (dd * y1.y + acc.y);
        y.z = dd * (dd * y1.z + acc.z);
        y.w = dd * (dd * y1.w + acc.w);
        *(reinterpret_cast<float4*>(&g_Y2[node * OUTP]) + ol) = y;
    } else if (ol == 3) {
        g_cnt[node] = 0;                 // replay invariant
    }
}

// 5: emb_b = relu(Y2 + s*c + b2);  out = [emb_a, emb_b] @ Wc + bc
__global__ void k_final(const float* __restrict__ emb_a, const float* __restrict__ b2,
                        const float* __restrict__ Wc, const float* __restrict__ bc,
                        float* __restrict__ out, int n) {
    __shared__ float wsm[CDIM * NCLASS];
    __shared__ float bsm[NCLASS];
    __shared__ float csm[OUTH];
    __shared__ float b2sm[OUTH];
    for (int t = threadIdx.x; t < CDIM * NCLASS; t += blockDim.x) wsm[t] = Wc[t];
    if (threadIdx.x < NCLASS) bsm[threadIdx.x] = bc[threadIdx.x];
    if (threadIdx.x < OUTH) { csm[threadIdx.x] = g_c[threadIdx.x]; b2sm[threadIdx.x] = b2[threadIdx.x]; }
    __syncthreads();
    int i = blockIdx.x * blockDim.x + threadIdx.x;
    if (i >= n) return;

    float acc[NCLASS];
#pragma unroll
    for (int k = 0; k < NCLASS; k++) acc[k] = bsm[k];

    const float4* ea = reinterpret_cast<const float4*>(&emb_a[(size_t)i * NCLASS]);
#pragma unroll
    for (int m4 = 0; m4 < NCLASS / 4; m4++) {
        float4 v = ea[m4];
        float vv[4] = {v.x, v.y, v.z, v.w};
#pragma unroll
        for (int q = 0; q < 4; q++) {
            float a = vv[q];
            int m = m4 * 4 + q;
#pragma unroll
            for (int k = 0; k < NCLASS; k++) acc[k] += a * wsm[m * NCLASS + k];
        }
    }

    float di = g_dinv[i];
    float s = di * (di + g_sdin[i]);
#pragma unroll
    for (int j = 0; j < OUTH; j++) {
        float h = g_Y2[(size_t)i * OUTP + j] + s * csm[j] + b2sm[j];
        h = fmaxf(h, 0.0f);
#pragma unroll
        for (int k = 0; k < NCLASS; k++) acc[k] += h * wsm[(NCLASS + j) * NCLASS + k];
    }

    float4* op = reinterpret_cast<float4*>(&out[(size_t)i * NCLASS]);
#pragma unroll
    for (int q = 0; q < NCLASS / 4; q++)
        op[q] = make_float4(acc[q * 4], acc[q * 4 + 1], acc[q * 4 + 2], acc[q * 4 + 3]);
}

// ---------------- launch ----------------
extern "C" void kernel_launch(void* const* d_in, const int* in_sizes, int n_in,
                              void* d_out, int out_size) {
    const float* x     = (const float*)d_in[0];
    const int*   ei    = (const int*)d_in[1];     // int32 (JAX x64 disabled)
    const float* emb_a = (const float*)d_in[2];
    const float* W1    = (const float*)d_in[3];
    const float* b1    = (const float*)d_in[4];
    const float* W2    = (const float*)d_in[5];
    const float* b2    = (const float*)d_in[6];
    const float* Wc    = (const float*)d_in[7];
    const float* bc    = (const float*)d_in[8];
    float* out = (float*)d_out;

    int n  = in_sizes[0] / INH;   // 100000
    int e  = in_sizes[1] / 2;     // 1600000
    int nh = in_sizes[4];         // 256

    const int TB = 256;
    int nblk = (n + 1023) / 1024;             // 98
    k_deg    <<<(e / 4 + TB - 1) / TB, TB>>>(ei + e, e);                 // 0
    k_scanM  <<<nblk, 256>>>(x, W1, W2, b1, nh, n);                      // 1
    k_scatter<<<(e / 4 + TB - 1) / TB, TB>>>(ei, e);                     // 2
    k_agg0   <<<(n * 8 + TB - 1) / TB, TB>>>(n);                         // 3 <- ncu
    k_agg1   <<<(n * 8 + TB - 1) / TB, TB>>>(n);                         // 4
    k_final  <<<(n + TB - 1) / TB, TB>>>(emb_a, b2, Wc, bc, out, n);     // 5
}

// round 10
// speedup vs baseline: 1.3632x; 1.0383x over previous
#include <cuda_runtime.h>

#define NMAX   100000
#define EMAX   1600000
#define INH    18
#define OUTH   11
#define OUTP   12      // 11 features + dinv in slot 11
#define NCLASS 40
#define CDIM   51      // NCLASS + OUTH
#define NBLK   98      // ceil(NMAX/1024)

// ---------------- scratch (device globals; zero-init BSS) ----------------
__device__ int   g_cnt   [NMAX];       // in-degree; re-zeroed by agg1 each run
__device__ int   g_rowptr[NMAX];       // block-local excl scan; bumped by scatter
__device__ int   g_blksum[NBLK];
__device__ int   g_blkoff[NBLK];
__device__ int   g_ctr;                // ticket; reset by scanM last block
__device__ float g_dinv[NMAX];
__device__ float g_sdin[NMAX];
__device__ __align__(16) float g_M  [NMAX * OUTP];   // [m0..m10, dinv]
__device__ __align__(16) float g_Y1 [NMAX * OUTP];   // [y0..y10, dinv]
__device__ __align__(16) float g_Y2 [NMAX * OUTP];
__device__ int   g_esrc[EMAX];         // CSR src ids (dst-major)
__device__ float g_c  [OUTH];          // b1 @ W2

// ---------------- kernels ----------------

// 0: in-degree histogram, 4 edges/thread
__global__ void k_deg(const int* __restrict__ dst, int e) {
    int i = blockIdx.x * blockDim.x + threadIdx.x;
    int base = i * 4;
    if ((e & 3) == 0 && base + 3 < e) {
        int4 d4 = *reinterpret_cast<const int4*>(dst + base);
        atomicAdd(&g_cnt[d4.x], 1);
        atomicAdd(&g_cnt[d4.y], 1);
        atomicAdd(&g_cnt[d4.z], 1);
        atomicAdd(&g_cnt[d4.w], 1);
    } else {
        for (int k = base; k < e && k < base + 4; k++) atomicAdd(&g_cnt[dst[k]], 1);
    }
}

// 1: fused: block-local scan of cnt -> rowptr; W12; dinv+M; last block scans blksums
__global__ void k_scanM(const float* __restrict__ x,
                        const float* __restrict__ W1, const float* __restrict__ W2,
                        const float* __restrict__ b1, int nh, int n) {
    __shared__ float w[INH * OUTH];
    __shared__ int   sh[256];
    __shared__ int   sh2[128];
    __shared__ int   lastblk;
    int b = blockIdx.x, t = threadIdx.x;
    int base = b * 1024 + t * 4;

    int v0 = 0, v1 = 0, v2 = 0, v3 = 0;
    if (base + 3 < n) {
        int4 c = *reinterpret_cast<const int4*>(&g_cnt[base]);
        v0 = c.x; v1 = c.y; v2 = c.z; v3 = c.w;
    } else {
        if (base     < n) v0 = g_cnt[base];
        if (base + 1 < n) v1 = g_cnt[base + 1];
        if (base + 2 < n) v2 = g_cnt[base + 2];
        if (base + 3 < n) v3 = g_cnt[base + 3];
    }
    int tsum = v0 + v1 + v2 + v3;
    sh[t] = tsum;
    __syncthreads();
    for (int off = 1; off < 256; off <<= 1) {
        int xx = (t >= off) ? sh[t - off] : 0;
        __syncthreads();
        sh[t] += xx;
        __syncthreads();
    }
    int excl = sh[t] - tsum;
    if (t == 255) g_blksum[b] = sh[255];
    if (base     < n) g_rowptr[base]     = excl;
    if (base + 1 < n) g_rowptr[base + 1] = excl + v0;
    if (base + 2 < n) g_rowptr[base + 2] = excl + v0 + v1;
    if (base + 3 < n) g_rowptr[base + 3] = excl + v0 + v1 + v2;

    if (t < INH * OUTH) {
        int i = t / OUTH, j = t % OUTH;
        float s = 0.f;
        for (int k = 0; k < nh; k++) s += W1[i * nh + k] * W2[k * OUTH + j];
        w[t] = s;
    } else if (b == 0 && t < INH * OUTH + OUTH) {
        int j = t - INH * OUTH;
        float s = 0.f;
        for (int k = 0; k < nh; k++) s += b1[k] * W2[k * OUTH + j];
        g_c[j] = s;
    }
    __syncthreads();

    int cn[4] = {v0, v1, v2, v3};
#pragma unroll
    for (int q = 0; q < 4; q++) {
        int node = base + q;
        if (node >= n) break;
        float di = rsqrtf((float)(cn[q] + 1));
        g_dinv[node] = di;
        float xr[INH];
#pragma unroll
        for (int k = 0; k < INH; k++) xr[k] = x[node * INH + k];
        float o[OUTP];
#pragma unroll
        for (int j = 0; j < OUTH; j++) {
            float s = 0.f;
#pragma unroll
            for (int k = 0; k < INH; k++) s += xr[k] * w[k * OUTH + j];
            o[j] = s;
        }
        o[OUTH] = di;
        float4* mp = reinterpret_cast<float4*>(&g_M[node * OUTP]);
        mp[0] = make_float4(o[0], o[1], o[2],  o[3]);
        mp[1] = make_float4(o[4], o[5], o[6],  o[7]);
        mp[2] = make_float4(o[8], o[9], o[10], o[11]);
    }

    __syncthreads();
    if (t == 0) {
        __threadfence();
        lastblk = (atomicAdd(&g_ctr, 1) == gridDim.x - 1) ? 1 : 0;
    }
    __syncthreads();
    if (lastblk) {
        __threadfence();
        int v = 0;
        if (t < NBLK) v = g_blksum[t];
        if (t < 128) sh2[t] = (t < NBLK) ? v : 0;
        __syncthreads();
        for (int off = 1; off < 128; off <<= 1) {
            int xx = 0;
            if (t < 128 && t >= off) xx = sh2[t - off];
            __syncthreads();
            if (t < 128) sh2[t] += xx;
            __syncthreads();
        }
        if (t < NBLK) g_blkoff[t] = sh2[t] - v;
        if (t == 0) g_ctr = 0;
    }
}

// 2: scatter src into CSR (atomic directly on rowptr)
__global__ void k_scatter(const int* __restrict__ ei, int e) {
    int i = blockIdx.x * blockDim.x + threadIdx.x;
    int base = i * 4;
    if ((e & 3) == 0 && base + 3 < e) {
        int4 s4 = *reinterpret_cast<const int4*>(ei + base);
        int4 d4 = *reinterpret_cast<const int4*>(ei + e + base);
        int p;
        p = atomicAdd(&g_rowptr[d4.x], 1) + g_blkoff[d4.x >> 10]; g_esrc[p] = s4.x;
        p = atomicAdd(&g_rowptr[d4.y], 1) + g_blkoff[d4.y >> 10]; g_esrc[p] = s4.y;
        p = atomicAdd(&g_rowptr[d4.z], 1) + g_blkoff[d4.z >> 10]; g_esrc[p] = s4.z;
        p = atomicAdd(&g_rowptr[d4.w], 1) + g_blkoff[d4.w >> 10]; g_esrc[p] = s4.w;
    } else {
        for (int k = base; k < e && k < base + 4; k++) {
            int s = ei[k], d = ei[e + k];
            int p = atomicAdd(&g_rowptr[d], 1) + g_blkoff[d >> 10];
            g_esrc[p] = s;
        }
    }
}

// 3: 4 lanes/node, 2-edge software pipeline (aligned int2 esrc reads).
//    Y1 = dd*(dd*M + sum ds*M[s]); slot11 = dd; sdin = sum ds (lane 3)
__global__ void k_agg0(int n) {
    int tid  = blockIdx.x * blockDim.x + threadIdx.x;
    int node = tid >> 2;
    int lane = tid & 3;
    if (node >= n) return;
    unsigned gmask = 0xFu << (threadIdx.x & 28);
    int   cnt = g_cnt[node];
    int   beg = g_rowptr[node] + g_blkoff[node >> 10] - cnt;  // rowptr was bumped
    float dd  = g_dinv[node];
    float4 acc = make_float4(0.f, 0.f, 0.f, 0.f);
    float  sds = 0.f;
    int k = 0;
    if ((beg & 1) && cnt > 0) {                 // peel to align int2 loads
        int s = __ldg(&g_esrc[beg]);
        float4 v = make_float4(0.f, 0.f, 0.f, 0.f);
        if (lane < 3) v = __ldg(reinterpret_cast<const float4*>(&g_M[s * OUTP]) + lane);
        float ds = __shfl_sync(gmask, v.w, 2, 4);
        acc.x += ds * v.x; acc.y += ds * v.y;
        acc.z += ds * v.z; acc.w += ds * v.w;
        sds += ds;
        k = 1;
    }
    int pairs = (cnt - k) >> 1;
    const int2* ep = reinterpret_cast<const int2*>(&g_esrc[beg + k]);
#pragma unroll 2
    for (int p = 0; p < pairs; p++) {
        int2 ss = __ldg(&ep[p]);
        float4 v0 = make_float4(0.f, 0.f, 0.f, 0.f);
        float4 v1 = make_float4(0.f, 0.f, 0.f, 0.f);
        if (lane < 3) {
            v0 = __ldg(reinterpret_cast<const float4*>(&g_M[ss.x * OUTP]) + lane);
            v1 = __ldg(reinterpret_cast<const float4*>(&g_M[ss.y * OUTP]) + lane);
        }
        float ds0 = __shfl_sync(gmask, v0.w, 2, 4);
        float ds1 = __shfl_sync(gmask, v1.w, 2, 4);
        acc.x += ds0 * v0.x + ds1 * v1.x;
        acc.y += ds0 * v0.y + ds1 * v1.y;
        acc.z += ds0 * v0.z + ds1 * v1.z;
        acc.w += ds0 * v0.w + ds1 * v1.w;
        sds += ds0 + ds1;
    }
    k += pairs * 2;
    if (k < cnt) {                              // tail edge
        int s = __ldg(&g_esrc[beg + k]);
        float4 v = make_float4(0.f, 0.f, 0.f, 0.f);
        if (lane < 3) v = __ldg(reinterpret_cast<const float4*>(&g_M[s * OUTP]) + lane);
        float ds = __shfl_sync(gmask, v.w, 2, 4);
        acc.x += ds * v.x; acc.y += ds * v.y;
        acc.z += ds * v.z; acc.w += ds * v.w;
        sds += ds;
    }
    if (lane < 3) {
        float4 m = *(reinterpret_cast<const float4*>(&g_M[node * OUTP]) + lane);
        float4 y;
        y.x = dd * (dd * m.x + acc.x);
        y.y = dd * (dd * m.y + acc.y);
        y.z = dd * (dd * m.z + acc.z);
        y.w = dd * (dd * m.w + acc.w);
        if (lane == 2) y.w = dd;         // keep dinv packed in Y1 slot 11
        *(reinterpret_cast<float4*>(&g_Y1[node * OUTP]) + lane) = y;
    } else {
        g_sdin[node] = sds;
    }
}

// 4: same pipeline on Y1 -> Y2; zero cnt for next run
__global__ void k_agg1(int n) {
    int tid  = blockIdx.x * blockDim.x + threadIdx.x;
    int node = tid >> 2;
    int lane = tid & 3;
    if (node >= n) return;
    unsigned gmask = 0xFu << (threadIdx.x & 28);
    int   cnt = g_cnt[node];
    int   beg = g_rowptr[node] + g_blkoff[node >> 10] - cnt;
    float dd  = g_dinv[node];
    float4 acc = make_float4(0.f, 0.f, 0.f, 0.f);
    int k = 0;
    if ((beg & 1) && cnt > 0) {
        int s = __ldg(&g_esrc[beg]);
        float4 v = make_float4(0.f, 0.f, 0.f, 0.f);
        if (lane < 3) v = __ldg(reinterpret_cast<const float4*>(&g_Y1[s * OUTP]) + lane);
        float ds = __shfl_sync(gmask, v.w, 2, 4);
        acc.x += ds * v.x; acc.y += ds * v.y;
        acc.z += ds * v.z; acc.w += ds * v.w;
        k = 1;
    }
    int pairs = (cnt - k) >> 1;
    const int2* ep = reinterpret_cast<const int2*>(&g_esrc[beg + k]);
#pragma unroll 2
    for (int p = 0; p < pairs; p++) {
        int2 ss = __ldg(&ep[p]);
        float4 v0 = make_float4(0.f, 0.f, 0.f, 0.f);
        float4 v1 = make_float4(0.f, 0.f, 0.f, 0.f);
        if (lane < 3) {
            v0 = __ldg(reinterpret_cast<const float4*>(&g_Y1[ss.x * OUTP]) + lane);
            v1 = __ldg(reinterpret_cast<const float4*>(&g_Y1[ss.y * OUTP]) + lane);
        }
        float ds0 = __shfl_sync(gmask, v0.w, 2, 4);
        float ds1 = __shfl_sync(gmask, v1.w, 2, 4);
        acc.x += ds0 * v0.x + ds1 * v1.x;
        acc.y += ds0 * v0.y + ds1 * v1.y;
        acc.z += ds0 * v0.z + ds1 * v1.z;
        acc.w += ds0 * v0.w + ds1 * v1.w;
    }
    k += pairs * 2;
    if (k < cnt) {
        int s = __ldg(&g_esrc[beg + k]);
        float4 v = make_float4(0.f, 0.f, 0.f, 0.f);
        if (lane < 3) v = __ldg(reinterpret_cast<const float4*>(&g_Y1[s * OUTP]) + lane);
        float ds = __shfl_sync(gmask, v.w, 2, 4);
        acc.x += ds * v.x; acc.y += ds * v.y;
        acc.z += ds * v.z; acc.w += ds * v.w;
    }
    if (lane < 3) {
        float4 y1 = *(reinterpret_cast<const float4*>(&g_Y1[node * OUTP]) + lane);
        float4 y;
        y.x = dd * (dd * y1.x + acc.x);
        y.y = dd * (dd * y1.y + acc.y);
        y.z = dd * (dd * y1.z + acc.z);
        y.w = dd * (dd * y1.w + acc.w);
        *(reinterpret_cast<float4*>(&g_Y2[node * OUTP]) + lane) = y;
    } else {
        g_cnt[node] = 0;                 // replay invariant
    }
}

// 5: emb_b = relu(Y2 + s*c + b2);  out = [emb_a, emb_b] @ Wc + bc
__global__ void k_final(const float* __restrict__ emb_a, const float* __restrict__ b2,
                        const float* __restrict__ Wc, const float* __restrict__ bc,
                        float* __restrict__ out, int n) {
    __shared__ float wsm[CDIM * NCLASS];
    __shared__ float bsm[NCLASS];
    __shared__ float csm[OUTH];
    __shared__ float b2sm[OUTH];
    for (int t = threadIdx.x; t < CDIM * NCLASS; t += blockDim.x) wsm[t] = Wc[t];
    if (threadIdx.x < NCLASS) bsm[threadIdx.x] = bc[threadIdx.x];
    if (threadIdx.x < OUTH) { csm[threadIdx.x] = g_c[threadIdx.x]; b2sm[threadIdx.x] = b2[threadIdx.x]; }
    __syncthreads();
    int i = blockIdx.x * blockDim.x + threadIdx.x;
    if (i >= n) return;

    float acc[NCLASS];
#pragma unroll
    for (int k = 0; k < NCLASS; k++) acc[k] = bsm[k];

    const float4* ea = reinterpret_cast<const float4*>(&emb_a[(size_t)i * NCLASS]);
#pragma unroll
    for (int m4 = 0; m4 < NCLASS / 4; m4++) {
        float4 v = ea[m4];
        float vv[4] = {v.x, v.y, v.z, v.w};
#pragma unroll
        for (int q = 0; q < 4; q++) {
            float a = vv[q];
            int m = m4 * 4 + q;
#pragma unroll
            for (int k = 0; k < NCLASS; k++) acc[k] += a * wsm[m * NCLASS + k];
        }
    }

    float di = g_dinv[i];
    float s = di * (di + g_sdin[i]);
#pragma unroll
    for (int j = 0; j < OUTH; j++) {
        float h = g_Y2[(size_t)i * OUTP + j] + s * csm[j] + b2sm[j];
        h = fmaxf(h, 0.0f);
#pragma unroll
        for (int k = 0; k < NCLASS; k++) acc[k] += h * wsm[(NCLASS + j) * NCLASS + k];
    }

    float4* op = reinterpret_cast<float4*>(&out[(size_t)i * NCLASS]);
#pragma unroll
    for (int q = 0; q < NCLASS / 4; q++)
        op[q] = make_float4(acc[q * 4], acc[q * 4 + 1], acc[q * 4 + 2], acc[q * 4 + 3]);
}

// ---------------- launch ----------------
extern "C" void kernel_launch(void* const* d_in, const int* in_sizes, int n_in,
                              void* d_out, int out_size) {
    const float* x     = (const float*)d_in[0];
    const int*   ei    = (const int*)d_in[1];     // int32 (JAX x64 disabled)
    const float* emb_a = (const float*)d_in[2];
    const float* W1    = (const float*)d_in[3];
    const float* b1    = (const float*)d_in[4];
    const float* W2    = (const float*)d_in[5];
    const float* b2    = (const float*)d_in[6];
    const float* Wc    = (const float*)d_in[7];
    const float* bc    = (const float*)d_in[8];
    float* out = (float*)d_out;

    int n  = in_sizes[0] / INH;   // 100000
    int e  = in_sizes[1] / 2;     // 1600000
    int nh = in_sizes[4];         // 256

    const int TB = 256;
    int nblk = (n + 1023) / 1024;             // 98
    k_deg    <<<(e / 4 + TB - 1) / TB, TB>>>(ei + e, e);                 // 0
    k_scanM  <<<nblk, 256>>>(x, W1, W2, b1, nh, n);                      // 1
    k_scatter<<<(e / 4 + TB - 1) / TB, TB>>>(ei, e);                     // 2
    k_agg0   <<<(n * 4 + TB - 1) / TB, TB>>>(n);                         // 3 <- ncu
    k_agg1   <<<(n * 4 + TB - 1) / TB, TB>>>(n);                         // 4
    k_final  <<<(n + TB - 1) / TB, TB>>>(emb_a, b2, Wc, bc, out, n);     // 5
}